// round 15
// baseline (speedup 1.0000x reference)
#include <cuda_runtime.h>
#include <cstdint>

#define NPTS   16384
#define NBINS  256
#define CAP    512                 // padded slots per bin (center mean ~306)
#define ZMIN   (-6.0f)
#define DZ     (12.0f / 256.0f)
#define INV_DZ (256.0f / 12.0f)
#define GRID   128
#define TPB    1024                // 32 warps/CTA -> 4096 warps
#define NWARPS (GRID * (TPB / 32))
#define NGROUPS (2 * NBINS * (CAP / 32))   // dir x chunk x bin = 8192

// Zero-initialized at load; finalizer resets cursors each replay.
// Barrier state (g_arrive, g_flag, g_done) is monotonic -> never reset.
__device__ int      g_cursor[2][NBINS];
__device__ float4   g_bins[2][NBINS * CAP];   // (-2x,-2y,-2z,|p|^2)
__device__ float    g_sum;
__device__ unsigned g_done;
__device__ unsigned g_arrive;
__device__ unsigned g_flag[GRID];

__device__ __forceinline__ int zbin(float z) {
    int b = (int)floorf((z - ZMIN) * INV_DZ);
    return max(0, min(NBINS - 1, b));
}

// ---- L2-coherent primitives ------------------------------------------------
__device__ __forceinline__ unsigned ld_acq(unsigned* p) {
    unsigned v;
    asm volatile("ld.acquire.gpu.global.u32 %0, [%1];" : "=r"(v) : "l"(p) : "memory");
    return v;
}
__device__ __forceinline__ void st_rel(unsigned* p, unsigned v) {
    asm volatile("st.release.gpu.global.u32 [%0], %1;" :: "l"(p), "r"(v) : "memory");
}
__device__ __forceinline__ unsigned atom_add_acqrel(unsigned* p, unsigned v) {
    unsigned o;
    asm volatile("atom.add.acq_rel.gpu.global.u32 %0, [%1], %2;"
                 : "=r"(o) : "l"(p), "r"(v) : "memory");
    return o;
}

// Grid barrier v3: parallel distributed release (R10-proven).
// GRID=128 <= 148 SMs -> all CTAs co-resident in wave 1.
__device__ __forceinline__ void grid_barrier() {
    __shared__ unsigned sh_gen;
    __shared__ int      sh_lastb;
    __syncthreads();
    if (threadIdx.x == 0) {
        unsigned my = ld_acq(&g_flag[blockIdx.x]);
        sh_gen = my;
        __threadfence();
        unsigned old = atom_add_acqrel(&g_arrive, 1u);
        sh_lastb = ((old + 1u) % GRID == 0u);
    }
    __syncthreads();
    if (sh_lastb) {
        if (threadIdx.x < GRID)
            st_rel(&g_flag[threadIdx.x], sh_gen + 1u);   // 128 stores in parallel
    } else if (threadIdx.x == 0) {
        unsigned gen = sh_gen;
        while (ld_acq(&g_flag[blockIdx.x]) == gen) __nanosleep(64);
    }
    __syncthreads();
}

// Lockstep broadcast scan: ALL lanes read the SAME candidate (1 wavefront per
// load) and test it against their OWN source point -> 32 pair-tests per ~5
// warp-instructions. Two accumulators break the fminf dependency chain.
__device__ __forceinline__ void scan_bin_bcast(const float4* __restrict__ T,
                                               int base, int n,
                                               float sx, float sy, float sz,
                                               float& m) {
    float ma = 3.4e38f, mb = 3.4e38f;
    int j = 0;
#pragma unroll 2
    for (; j + 2 <= n; j += 2) {
        float4 ta = T[base + j];
        float4 tb = T[base + j + 1];
        float da = fmaf(sx, ta.x, ta.w);
        float db = fmaf(sx, tb.x, tb.w);
        da = fmaf(sy, ta.y, da);
        db = fmaf(sy, tb.y, db);
        da = fmaf(sz, ta.z, da);
        db = fmaf(sz, tb.z, db);
        ma = fminf(ma, da);
        mb = fminf(mb, db);
    }
    if (j < n) {
        float4 ta = T[base + j];
        float da = fmaf(sx, ta.x, ta.w);
        da = fmaf(sy, ta.y, da);
        da = fmaf(sz, ta.z, da);
        ma = fminf(ma, da);
    }
    m = fminf(m, fminf(ma, mb));
}

__global__ void __launch_bounds__(TPB, 1) chamfer_fused(
    const float* __restrict__ pred, const float* __restrict__ tgt,
    float* __restrict__ out)
{
    __shared__ int   sh_cnt[2 * NBINS];
    __shared__ float red[TPB];
    __shared__ int   sh_last;

    const int tid  = threadIdx.x;
    const int lane = tid & 31;

    // ---- Phase A: scatter into padded z-bins (coalesced reads) -------------
    if (tid < 256) {
        const int gidx = blockIdx.x * 256 + tid;    // 0..32767
        const int pdir = gidx >> 14;
        const int pi   = gidx & (NPTS - 1);
        const float* __restrict__ P = pdir ? tgt : pred;
        const float px = P[3 * pi + 0];
        const float py = P[3 * pi + 1];
        const float pz = P[3 * pi + 2];
        const int  b = zbin(pz);
        const int slot = atomicAdd(&g_cursor[pdir][b], 1);
        if (slot < CAP)
            g_bins[pdir][(b << 9) + slot] =
                make_float4(-2.0f * px, -2.0f * py, -2.0f * pz,
                            px * px + py * py + pz * pz);
    }

    grid_barrier();    // the ONLY device-wide sync

    if (tid < 2 * NBINS) sh_cnt[tid] = min(((int*)g_cursor)[tid], CAP);
    __syncthreads();

    // ---- Phase B: warp = 32 slots of ONE source bin; lockstep candidates ---
    const int wid = blockIdx.x * (TPB / 32) + (tid >> 5);   // 0..4095
    float acc = 0.0f;

#pragma unroll 1
    for (int grp = wid; grp < NGROUPS; grp += NWARPS) {
        const int dir   = grp >> 12;            // warp-uniform
        const int rem   = grp & 4095;
        const int chunk = rem >> 8;             // bin-major: heavy bins spread
        const int bin   = rem & 255;

        const int cnt_s = sh_cnt[dir * NBINS + bin];
        const int s0    = chunk * 32;
        if (s0 >= cnt_s) continue;              // empty chunk (warp-uniform skip)

        const bool valid = (s0 + lane) < cnt_s;
        float4 a = g_bins[dir][(bin << 9) + s0 + lane];   // in-pad always
        {   // invalid lanes borrow the first valid lane's point (discarded later)
            const unsigned vm = __ballot_sync(0xFFFFFFFFu, valid);
            const int src = __ffs(vm) - 1;
            float bx = __shfl_sync(0xFFFFFFFFu, a.x, src);
            float by = __shfl_sync(0xFFFFFFFFu, a.y, src);
            float bz = __shfl_sync(0xFFFFFFFFu, a.z, src);
            float bw = __shfl_sync(0xFFFFFFFFu, a.w, src);
            if (!valid) { a.x = bx; a.y = by; a.z = bz; a.w = bw; }
        }
        const float sx = -0.5f * a.x;
        const float sy = -0.5f * a.y;
        const float sz = -0.5f * a.z;
        const float sn = a.w;
        const float o  = sz - (ZMIN + (float)bin * DZ);   // in-bin offset (per lane)

        const int tdir = dir ^ 1;
        const float4* __restrict__ T = g_bins[tdir];
        const int* cnt = &sh_cnt[tdir * NBINS];

        float m = 3.4e38f;
        scan_bin_bcast(T, bin << 9, cnt[bin], sx, sy, sz, m);

        // Symmetric ring expansion: trip count decided by ballot of per-lane
        // certificates; scanned bins are warp-uniform -> no divergence.
        int K = 0;
        while (true) {
            float glo = (bin - K > 0)         ? (o + (float)K * DZ)       : 1e30f;
            float ghi = (bin + K < NBINS - 1) ? ((float)(K + 1) * DZ - o) : 1e30f;
            float g = fminf(glo, ghi);
            bool need = valid && (sn + m > g * g);   // inf*inf -> never need
            if (!__any_sync(0xFFFFFFFFu, need)) break;
            K++;
            const int bl = bin - K;
            const int bh = bin + K;
            if (bl >= 0)    scan_bin_bcast(T, bl << 9, cnt[bl], sx, sy, sz, m);
            if (bh < NBINS) scan_bin_bcast(T, bh << 9, cnt[bh], sx, sy, sz, m);
        }
        if (valid) acc += sn + m;               // = min_j ||s - t_j||^2
    }

    // ---- Phase C: reduce + last-block finalize (parallel reset) ------------
    red[tid] = acc;
    __syncthreads();
    for (int s = TPB / 2; s > 0; s >>= 1) {
        if (tid < s) red[tid] += red[tid + s];
        __syncthreads();
    }
    if (tid == 0) {
        atomicAdd(&g_sum, red[0]);
        sh_last = ((atom_add_acqrel(&g_done, 1u) + 1u) % GRID == 0u);
    }
    __syncthreads();
    if (sh_last) {
        if (tid == 0) {
            float total = atomicExch(&g_sum, 0.0f);
            out[0] = total / (float)(2 * NPTS);   // (mean_pt + mean_tp)/2
        }
        for (int c = tid; c < 2 * NBINS; c += TPB)
            ((int*)g_cursor)[c] = 0;              // reset for next replay
    }
}

extern "C" void kernel_launch(void* const* d_in, const int* in_sizes, int n_in,
                              void* d_out, int out_size)
{
    const float* pred = (const float*)d_in[0];
    const float* tgt  = (const float*)d_in[1];
    float* out = (float*)d_out;

    chamfer_fused<<<GRID, TPB>>>(pred, tgt, out);
}

// round 16
// speedup vs baseline: 1.5013x; 1.5013x over previous
#include <cuda_runtime.h>
#include <cstdint>

#define NPTS   16384
#define NBINS  256
#define CAP    512                 // padded slots per bin (center mean ~306)
#define ZMIN   (-6.0f)
#define DZ     (12.0f / 256.0f)
#define INV_DZ (256.0f / 12.0f)
#define GRID   128
#define TPB    1024                // 32 warps/CTA -> 4096 warps
#define NWARPS (GRID * (TPB / 32))
#define NGROUPS (2 * NBINS * (CAP / 32))   // dir x chunk x bin = 8192

// Zero-initialized at load; finalizer resets cursors each replay.
// Barrier state (g_arrive, g_flag, g_done) is monotonic -> never reset.
__device__ int      g_cursor[2][NBINS];
__device__ float4   g_bins[2][NBINS * CAP];   // (-2x,-2y,-2z,|p|^2)
__device__ float    g_sum;
__device__ unsigned g_done;
__device__ unsigned g_arrive;
__device__ unsigned g_flag[GRID];

__device__ __forceinline__ int zbin(float z) {
    int b = (int)floorf((z - ZMIN) * INV_DZ);
    return max(0, min(NBINS - 1, b));
}

// ---- L2-coherent primitives ------------------------------------------------
__device__ __forceinline__ unsigned ld_acq(unsigned* p) {
    unsigned v;
    asm volatile("ld.acquire.gpu.global.u32 %0, [%1];" : "=r"(v) : "l"(p) : "memory");
    return v;
}
__device__ __forceinline__ void st_rel(unsigned* p, unsigned v) {
    asm volatile("st.release.gpu.global.u32 [%0], %1;" :: "l"(p), "r"(v) : "memory");
}
__device__ __forceinline__ unsigned atom_add_acqrel(unsigned* p, unsigned v) {
    unsigned o;
    asm volatile("atom.add.acq_rel.gpu.global.u32 %0, [%1], %2;"
                 : "=r"(o) : "l"(p), "r"(v) : "memory");
    return o;
}

// Grid barrier v3: parallel distributed release (R10-proven).
// GRID=128 <= 148 SMs -> all CTAs co-resident in wave 1.
__device__ __forceinline__ void grid_barrier() {
    __shared__ unsigned sh_gen;
    __shared__ int      sh_lastb;
    __syncthreads();
    if (threadIdx.x == 0) {
        unsigned my = ld_acq(&g_flag[blockIdx.x]);
        sh_gen = my;
        __threadfence();
        unsigned old = atom_add_acqrel(&g_arrive, 1u);
        sh_lastb = ((old + 1u) % GRID == 0u);
    }
    __syncthreads();
    if (sh_lastb) {
        if (threadIdx.x < GRID)
            st_rel(&g_flag[threadIdx.x], sh_gen + 1u);   // 128 stores in parallel
    } else if (threadIdx.x == 0) {
        unsigned gen = sh_gen;
        while (ld_acq(&g_flag[blockIdx.x]) == gen) __nanosleep(64);
    }
    __syncthreads();
}

__device__ __forceinline__ float warp_min(float v) {
    v = fminf(v, __shfl_xor_sync(0xFFFFFFFFu, v, 16));
    v = fminf(v, __shfl_xor_sync(0xFFFFFFFFu, v, 8));
    v = fminf(v, __shfl_xor_sync(0xFFFFFFFFu, v, 4));
    v = fminf(v, __shfl_xor_sync(0xFFFFFFFFu, v, 2));
    v = fminf(v, __shfl_xor_sync(0xFFFFFFFFu, v, 1));
    return v;
}

// R11-style warp-cooperative bin scan: lanes stride the candidates (32 loads
// in flight per warp), all testing ONE shared source point.
__device__ __forceinline__ void scan_bin_warp(const float4* __restrict__ T,
                                              int base, int n, int lane,
                                              float sx, float sy, float sz,
                                              float& m) {
    float ma = 3.4e38f, mb = 3.4e38f;
    int j = lane;
    for (; j + 32 < n; j += 64) {
        float4 ta = T[base + j];
        float4 tb = T[base + j + 32];
        float da = fmaf(sx, ta.x, ta.w);
        float db = fmaf(sx, tb.x, tb.w);
        da = fmaf(sy, ta.y, da);
        db = fmaf(sy, tb.y, db);
        da = fmaf(sz, ta.z, da);
        db = fmaf(sz, tb.z, db);
        ma = fminf(ma, da);
        mb = fminf(mb, db);
    }
    if (j < n) {
        float4 ta = T[base + j];
        float da = fmaf(sx, ta.x, ta.w);
        da = fmaf(sy, ta.y, da);
        da = fmaf(sz, ta.z, da);
        ma = fminf(ma, da);
    }
    m = fminf(m, fminf(ma, mb));
}

__global__ void __launch_bounds__(TPB, 1) chamfer_fused(
    const float* __restrict__ pred, const float* __restrict__ tgt,
    float* __restrict__ out)
{
    __shared__ int   sh_cnt[2 * NBINS];
    __shared__ float red[TPB];
    __shared__ int   sh_last;

    const int tid  = threadIdx.x;
    const int lane = tid & 31;

    // ---- Phase A: scatter into padded z-bins (coalesced reads) -------------
    if (tid < 256) {
        const int gidx = blockIdx.x * 256 + tid;    // 0..32767
        const int pdir = gidx >> 14;
        const int pi   = gidx & (NPTS - 1);
        const float* __restrict__ P = pdir ? tgt : pred;
        const float px = P[3 * pi + 0];
        const float py = P[3 * pi + 1];
        const float pz = P[3 * pi + 2];
        const int  b = zbin(pz);
        const int slot = atomicAdd(&g_cursor[pdir][b], 1);
        if (slot < CAP)
            g_bins[pdir][(b << 9) + slot] =
                make_float4(-2.0f * px, -2.0f * py, -2.0f * pz,
                            px * px + py * py + pz * pz);
    }

    grid_barrier();    // the ONLY device-wide sync

    if (tid < 2 * NBINS) sh_cnt[tid] = min(((int*)g_cursor)[tid], CAP);
    __syncthreads();

    // ---- Phase B: warp owns 32 slots of ONE source bin; processes its points
    //      ONE AT A TIME with R11's lane-parallel candidate scan. All 32 points
    //      share the same ~5-bin window -> L1-resident after the first point.
    const int wid = blockIdx.x * (TPB / 32) + (tid >> 5);   // 0..4095
    float acc = 0.0f;

#pragma unroll 1
    for (int grp = wid; grp < NGROUPS; grp += NWARPS) {
        const int dir   = grp >> 12;            // warp-uniform
        const int rem   = grp & 4095;
        const int chunk = rem >> 8;             // bin-major: heavy bins spread
        const int bin   = rem & 255;

        const int cnt_s = sh_cnt[dir * NBINS + bin];
        const int s0    = chunk * 32;
        if (s0 >= cnt_s) continue;              // empty chunk (warp-uniform skip)
        const int nv = min(32, cnt_s - s0);     // valid points in this group

        // Lane's own source point (clamped read stays inside the bin pad).
        const float4 a = g_bins[dir][(bin << 9) + s0 + min(lane, nv - 1)];
        const float msx = -0.5f * a.x;
        const float msy = -0.5f * a.y;
        const float msz = -0.5f * a.z;
        const float msn = a.w;

        const int tdir = dir ^ 1;
        const float4* __restrict__ T = g_bins[tdir];
        const int* cnt = &sh_cnt[tdir * NBINS];

#pragma unroll 1
        for (int p = 0; p < nv; p++) {
            // Broadcast point p to all lanes.
            const float sx = __shfl_sync(0xFFFFFFFFu, msx, p);
            const float sy = __shfl_sync(0xFFFFFFFFu, msy, p);
            const float sz = __shfl_sync(0xFFFFFFFFu, msz, p);
            const float sn = __shfl_sync(0xFFFFFFFFu, msn, p);
            const float zs = sz;

            float m = 3.4e38f;
            scan_bin_warp(T, bin << 9, cnt[bin], lane, sx, sy, sz, m);
            int lo = bin, hi = bin + 1;

            float wm;
            while (true) {
                wm = warp_min(m);               // identical in all lanes
                float dlo = (lo > 0)     ? (zs - (ZMIN + (float)lo * DZ)) : 1e30f;
                float dhi = (hi < NBINS) ? ((ZMIN + (float)hi * DZ) - zs) : 1e30f;
                float g = fminf(dlo, dhi);
                if (sn + wm <= g * g) break;    // inf*inf -> break
                int b;
                if (dlo < dhi) { lo--; b = lo; }
                else           { b = hi; hi++; }
                scan_bin_warp(T, b << 9, cnt[b], lane, sx, sy, sz, m);
            }
            if (lane == (p & 31)) acc += sn + wm;   // = min_j ||s - t_j||^2
        }
    }

    // ---- Phase C: reduce + last-block finalize (parallel reset) ------------
    red[tid] = acc;
    __syncthreads();
    for (int s = TPB / 2; s > 0; s >>= 1) {
        if (tid < s) red[tid] += red[tid + s];
        __syncthreads();
    }
    if (tid == 0) {
        atomicAdd(&g_sum, red[0]);
        sh_last = ((atom_add_acqrel(&g_done, 1u) + 1u) % GRID == 0u);
    }
    __syncthreads();
    if (sh_last) {
        if (tid == 0) {
            float total = atomicExch(&g_sum, 0.0f);
            out[0] = total / (float)(2 * NPTS);   // (mean_pt + mean_tp)/2
        }
        for (int c = tid; c < 2 * NBINS; c += TPB)
            ((int*)g_cursor)[c] = 0;              // reset for next replay
    }
}

extern "C" void kernel_launch(void* const* d_in, const int* in_sizes, int n_in,
                              void* d_out, int out_size)
{
    const float* pred = (const float*)d_in[0];
    const float* tgt  = (const float*)d_in[1];
    float* out = (float*)d_out;

    chamfer_fused<<<GRID, TPB>>>(pred, tgt, out);
}

// round 17
// speedup vs baseline: 4.8858x; 3.2545x over previous
#include <cuda_runtime.h>
#include <cstdint>

#define NPTS   16384
#define NBINS  256
#define ZMIN   (-6.0f)
#define DZ     (12.0f / 256.0f)
#define INV_DZ (256.0f / 12.0f)
#define GRID   128
#define TPB    1024                // 32 warps/CTA -> 4096 warps
#define RPT    8                   // sorted points per warp

// Zero-initialized at load; finalizer resets hist/cursor each replay.
// Barrier state (g_arrive, g_flag, g_done) is monotonic -> never reset.
__device__ int      g_hist[2][NBINS];
__device__ int      g_cursor[2][NBINS];
__device__ float4   g_sorted[2][NPTS];   // compact, z-bin order: (-2x,-2y,-2z,|p|^2)
__device__ float    g_sum;
__device__ unsigned g_done;
__device__ unsigned g_arrive;
__device__ unsigned g_flag[GRID];

__device__ __forceinline__ int zbin(float z) {
    int b = (int)floorf((z - ZMIN) * INV_DZ);
    return max(0, min(NBINS - 1, b));
}

// ---- L2-coherent primitives ------------------------------------------------
__device__ __forceinline__ unsigned ld_acq(unsigned* p) {
    unsigned v;
    asm volatile("ld.acquire.gpu.global.u32 %0, [%1];" : "=r"(v) : "l"(p) : "memory");
    return v;
}
__device__ __forceinline__ void st_rel(unsigned* p, unsigned v) {
    asm volatile("st.release.gpu.global.u32 [%0], %1;" :: "l"(p), "r"(v) : "memory");
}
__device__ __forceinline__ unsigned atom_add_acqrel(unsigned* p, unsigned v) {
    unsigned o;
    asm volatile("atom.add.acq_rel.gpu.global.u32 %0, [%1], %2;"
                 : "=r"(o) : "l"(p), "r"(v) : "memory");
    return o;
}

// Grid barrier v3: parallel distributed release (R10-proven).
// GRID=128 <= 148 SMs -> all CTAs co-resident in wave 1.
__device__ __forceinline__ void grid_barrier() {
    __shared__ unsigned sh_gen;
    __shared__ int      sh_lastb;
    __syncthreads();
    if (threadIdx.x == 0) {
        unsigned my = ld_acq(&g_flag[blockIdx.x]);
        sh_gen = my;
        __threadfence();
        unsigned old = atom_add_acqrel(&g_arrive, 1u);
        sh_lastb = ((old + 1u) % GRID == 0u);
    }
    __syncthreads();
    if (sh_lastb) {
        if (threadIdx.x < GRID)
            st_rel(&g_flag[threadIdx.x], sh_gen + 1u);   // 128 stores in parallel
    } else if (threadIdx.x == 0) {
        unsigned gen = sh_gen;
        while (ld_acq(&g_flag[blockIdx.x]) == gen) __nanosleep(64);
    }
    __syncthreads();
}

__device__ __forceinline__ float warp_min(float v) {
    v = fminf(v, __shfl_xor_sync(0xFFFFFFFFu, v, 16));
    v = fminf(v, __shfl_xor_sync(0xFFFFFFFFu, v, 8));
    v = fminf(v, __shfl_xor_sync(0xFFFFFFFFu, v, 4));
    v = fminf(v, __shfl_xor_sync(0xFFFFFFFFu, v, 2));
    v = fminf(v, __shfl_xor_sync(0xFFFFFFFFu, v, 1));
    return v;
}

// Lanes stride candidates [jb,je); each candidate tests vs 8 register points.
__device__ __forceinline__ void scan8(const float4* __restrict__ T,
                                      int jb, int je, int lane,
                                      const float sx[RPT], const float sy[RPT],
                                      const float sz[RPT], float m[RPT]) {
    for (int j = jb + lane; j < je; j += 32) {
        float4 t = T[j];
#pragma unroll
        for (int k = 0; k < RPT; k++) {
            float d = fmaf(sx[k], t.x, t.w);
            d = fmaf(sy[k], t.y, d);
            d = fmaf(sz[k], t.z, d);
            m[k] = fminf(m[k], d);
        }
    }
}

__global__ void __launch_bounds__(TPB, 1) chamfer_fused(
    const float* __restrict__ pred, const float* __restrict__ tgt,
    float* __restrict__ out)
{
    __shared__ int   sh_scan[2][NBINS];
    __shared__ int   sh_bs[2][NBINS + 1];
    __shared__ float red[TPB];
    __shared__ int   sh_last;

    const int tid  = threadIdx.x;
    const int lane = tid & 31;

    // ---- Phase 1: histogram (this CTA's 256 points) ------------------------
    float px, py, pz;
    int   pdir = 0, pbin = 0;
    if (tid < 256) {
        const int gidx = blockIdx.x * 256 + tid;   // 0..32767
        pdir = gidx >> 14;
        const int pi = gidx & (NPTS - 1);
        const float* __restrict__ P = pdir ? tgt : pred;
        px = P[3 * pi + 0];
        py = P[3 * pi + 1];
        pz = P[3 * pi + 2];
        pbin = zbin(pz);
        atomicAdd(&g_hist[pdir][pbin], 1);
    }

    grid_barrier();   // histogram complete

    // ---- Phase 2: redundant smem scan (identical in every CTA) + scatter ---
    {
        const int d = tid >> 8, b = tid & 255;      // threads 0..511 active
        int v = 0;
        if (tid < 512) { v = g_hist[d][b]; sh_scan[d][b] = v; }
        __syncthreads();
        for (int off = 1; off < NBINS; off <<= 1) {
            int add = (tid < 512 && b >= off) ? sh_scan[d][b - off] : 0;
            __syncthreads();
            if (tid < 512) sh_scan[d][b] += add;
            __syncthreads();
        }
        if (tid < 512) sh_bs[d][b] = sh_scan[d][b] - v;   // exclusive
        if (tid == 0) { sh_bs[0][NBINS] = NPTS; sh_bs[1][NBINS] = NPTS; }
        __syncthreads();
    }
    if (tid < 256) {
        const int pos = sh_bs[pdir][pbin] + atomicAdd(&g_cursor[pdir][pbin], 1);
        g_sorted[pdir][pos] = make_float4(-2.0f * px, -2.0f * py, -2.0f * pz,
                                          px * px + py * py + pz * pz);
    }

    grid_barrier();   // sorted arrays complete

    // ---- Phase 3: warp = 8 consecutive sorted points; register-blocked scan -
    const int w    = blockIdx.x * 32 + (tid >> 5);   // 0..4095
    const int dir  = w >> 11;                        // 2048 warps per direction
    const int tdir = dir ^ 1;
    const int idx0 = (w & 2047) * RPT;               // 8 z-adjacent points
    const int* bs  = sh_bs[tdir];
    const float4* __restrict__ T = g_sorted[tdir];

    float sx[RPT], sy[RPT], sz[RPT], sn[RPT], m[RPT];
    int lo = NBINS, hi = 0;
#pragma unroll
    for (int k = 0; k < RPT; k++) {
        float4 p = g_sorted[dir][idx0 + k];          // broadcast loads
        sx[k] = -0.5f * p.x;
        sy[k] = -0.5f * p.y;
        sz[k] = -0.5f * p.z;
        sn[k] = p.w;
        m[k]  = 3.4e38f;
        int b = zbin(sz[k]);
        lo = min(lo, b);
        hi = max(hi, b);
    }
    hi += 1;                                         // scanned bins = [lo, hi)

    scan8(T, bs[lo], bs[hi], lane, sx, sy, sz, m);

    float wm[RPT];
    while (true) {
#pragma unroll
        for (int k = 0; k < RPT; k++) wm[k] = warp_min(m[k]);
        const float zle = ZMIN + (float)lo * DZ;     // low scanned edge
        const float zhe = ZMIN + (float)hi * DZ;     // high scanned edge
        bool need = false;
        float dlo_min = 1e30f, dhi_min = 1e30f;
#pragma unroll
        for (int k = 0; k < RPT; k++) {
            float dlo = (lo > 0)     ? (sz[k] - zle) : 1e30f;
            float dhi = (hi < NBINS) ? (zhe - sz[k]) : 1e30f;
            float g = fminf(dlo, dhi);
            need = need || (sn[k] + wm[k] > g * g);  // inf^2 -> never
            dlo_min = fminf(dlo_min, dlo);
            dhi_min = fminf(dhi_min, dhi);
        }
        if (!need) break;                            // warp-uniform
        if (dlo_min < dhi_min) { lo--; scan8(T, bs[lo], bs[lo + 1], lane, sx, sy, sz, m); }
        else                   { scan8(T, bs[hi], bs[hi + 1], lane, sx, sy, sz, m); hi++; }
    }

    float acc = 0.0f;
    if (lane == 0) {
#pragma unroll
        for (int k = 0; k < RPT; k++) acc += sn[k] + wm[k];   // min_j ||s-t||^2
    }

    // ---- Phase 4: reduce + last-block finalize (parallel reset) ------------
    red[tid] = acc;
    __syncthreads();
    for (int s = TPB / 2; s > 0; s >>= 1) {
        if (tid < s) red[tid] += red[tid + s];
        __syncthreads();
    }
    if (tid == 0) {
        atomicAdd(&g_sum, red[0]);
        sh_last = ((atom_add_acqrel(&g_done, 1u) + 1u) % GRID == 0u);
    }
    __syncthreads();
    if (sh_last) {
        if (tid == 0) {
            float total = atomicExch(&g_sum, 0.0f);
            out[0] = total / (float)(2 * NPTS);      // (mean_pt + mean_tp)/2
        }
        for (int c = tid; c < 2 * NBINS; c += TPB) {
            ((int*)g_hist)[c]   = 0;                 // reset for next replay
            ((int*)g_cursor)[c] = 0;
        }
    }
}

extern "C" void kernel_launch(void* const* d_in, const int* in_sizes, int n_in,
                              void* d_out, int out_size)
{
    const float* pred = (const float*)d_in[0];
    const float* tgt  = (const float*)d_in[1];
    float* out = (float*)d_out;

    chamfer_fused<<<GRID, TPB>>>(pred, tgt, out);
}